// round 7
// baseline (speedup 1.0000x reference)
#include <cuda_runtime.h>
#include <cuda_bf16.h>
#include <math.h>
#include <stdint.h>

// ---------------------------------------------------------------------------
// Problem constants
// ---------------------------------------------------------------------------
#define B_SZ 4
#define T_SZ 64
#define N_SZ 128
#define HEADS 32
#define D_DIM 1024
#define K2 2048
#define M_TOTAL 32768              // B*T*N
#define NEFF 3072                  // fused QKV output cols

// ---------------------------------------------------------------------------
// Scratch carve-out (single __device__ blob; allocation-free rule)
// ---------------------------------------------------------------------------
#define OFF_QKV   ((size_t)0)                       // fp32 [32768,3072]
#define OFF_AO    (OFF_QKV  + (size_t)402653184)    // fp32 [32768,1024]
#define OFF_AHI   (OFF_AO   + (size_t)134217728)    // bf16 [32768,2048]
#define OFF_ALO   (OFF_AHI  + (size_t)134217728)
#define OFF_AOHI  (OFF_ALO  + (size_t)134217728)    // bf16 [32768,1024]
#define OFF_AOLO  (OFF_AOHI + (size_t)67108864)
#define OFF_WTHI  (OFF_AOLO + (size_t)67108864)     // bf16 [3072,2048]
#define OFF_WTLO  (OFF_WTHI + (size_t)12582912)
#define OFF_WOTHI (OFF_WTLO + (size_t)12582912)     // bf16 [1024,1024]
#define OFF_WOTLO (OFF_WOTHI + (size_t)2097152)
#define OFF_BIAS  (OFF_WOTLO + (size_t)2097152)     // fp32 [3072]
#define SCRATCH_BYTES (OFF_BIAS + (size_t)12288)

__device__ __align__(1024) unsigned char g_scratch[SCRATCH_BYTES];

// ---------------------------------------------------------------------------
// PTX helpers (base sm_100 features only)
// ---------------------------------------------------------------------------
static __device__ __forceinline__ unsigned smem_u32(const void* p) {
    unsigned r;
    asm("{ .reg .u64 t; cvta.to.shared.u64 t, %1; cvt.u32.u64 %0, t; }"
        : "=r"(r) : "l"(p));
    return r;
}
static __device__ __forceinline__ void cp16(unsigned dst, const void* src) {
    asm volatile("cp.async.cg.shared.global [%0], [%1], 16;"
                 :: "r"(dst), "l"(src) : "memory");
}
static __device__ __forceinline__ void cp_commit() {
    asm volatile("cp.async.commit_group;" ::: "memory");
}
static __device__ __forceinline__ void cp_wait2() {
    asm volatile("cp.async.wait_group 2;" ::: "memory");
}
static __device__ __forceinline__ void ldmx4(
    unsigned& r0, unsigned& r1, unsigned& r2, unsigned& r3, unsigned addr) {
    asm volatile("ldmatrix.sync.aligned.m8n8.x4.shared.b16 {%0,%1,%2,%3}, [%4];"
                 : "=r"(r0), "=r"(r1), "=r"(r2), "=r"(r3) : "r"(addr));
}
static __device__ __forceinline__ void mma16816(
    float* c, const unsigned* a, unsigned b0, unsigned b1) {
    asm volatile(
        "mma.sync.aligned.m16n8k16.row.col.f32.bf16.bf16.f32 "
        "{%0,%1,%2,%3}, {%4,%5,%6,%7}, {%8,%9}, {%0,%1,%2,%3};"
        : "+f"(c[0]), "+f"(c[1]), "+f"(c[2]), "+f"(c[3])
        : "r"(a[0]), "r"(a[1]), "r"(a[2]), "r"(a[3]), "r"(b0), "r"(b1));
}

// ---------------------------------------------------------------------------
// bf16 split-precision GEMM via mma.sync.
// C[M, cstride-window] = relu( A @ WT^T + bias ); K_eff = 3K regions:
// (Ahi,WThi), (Ahi,WTlo), (Alo,WThi).
// CTA tile 128x256, BK=32, 8 warps (warptile 64x64), 4-stage cp.async.
// ---------------------------------------------------------------------------
#define PADK 40                        // halves per padded smem row (80B)
#define A_ST_BYTES (128 * PADK * 2)    // 10240
#define B_ST_BYTES (256 * PADK * 2)    // 20480
#define ST_BYTES   (A_ST_BYTES + B_ST_BYTES)   // 30720
#define NSTG 4
#define GEMM_SMEM (NSTG * ST_BYTES)    // 122880

__global__ void __launch_bounds__(256, 1) mma_gemm(
    const __nv_bfloat16* __restrict__ Ahi,
    const __nv_bfloat16* __restrict__ Alo,
    const __nv_bfloat16* __restrict__ WThi,
    const __nv_bfloat16* __restrict__ WTlo,
    const float* __restrict__ bias,
    float* __restrict__ C,
    int K, int cstride)
{
    extern __shared__ __align__(16) unsigned char smem[];
    const unsigned sbase = smem_u32(smem);

    const int tid  = threadIdx.x;
    const int lane = tid & 31;
    const int warp = tid >> 5;
    const int wm   = warp >> 2;          // 0..1 (64-row slab)
    const int wn   = warp & 3;           // 0..3 (64-col slab)
    const int tileM = blockIdx.y * 128;
    const int tileN = blockIdx.x * 256;

    const int CPR = K >> 5;              // 32-wide K chunks per region
    const int NC  = 3 * CPR;

    float acc[4][8][4];
    #pragma unroll
    for (int mi = 0; mi < 4; mi++)
        #pragma unroll
        for (int ni = 0; ni < 8; ni++)
            #pragma unroll
            for (int e = 0; e < 4; e++) acc[mi][ni][e] = 0.f;

    // copy chunk kc into stage s. A: 128x32 (2 cp/thread); B: 256x32 (4 cp/thread)
    auto do_copy = [&](int kc, int s) {
        const int region = kc / CPR;
        const int klocal = (kc % CPR) << 5;
        const __nv_bfloat16* Asrc = (region < 2) ? Ahi : Alo;
        const __nv_bfloat16* Bsrc = (region == 1) ? WTlo : WThi;
        const unsigned stA = sbase + s * ST_BYTES;
        const unsigned stB = stA + A_ST_BYTES;
        #pragma unroll
        for (int i = 0; i < 2; i++) {
            int idx = tid + i * 256;          // 0..511
            int r = idx >> 2, c = idx & 3;
            cp16(stA + (r * PADK + c * 8) * 2,
                 Asrc + (size_t)(tileM + r) * K + klocal + c * 8);
        }
        #pragma unroll
        for (int i = 0; i < 4; i++) {
            int idx = tid + i * 256;          // 0..1023
            int r = idx >> 2, c = idx & 3;
            cp16(stB + (r * PADK + c * 8) * 2,
                 Bsrc + (size_t)(tileN + r) * K + klocal + c * 8);
        }
    };

    // prologue: 3 stages in flight
    #pragma unroll
    for (int p = 0; p < 3; p++) { do_copy(p, p); cp_commit(); }

    for (int kc = 0; kc < NC; kc++) {
        const int s = kc & (NSTG - 1);
        cp_wait2();                     // chunk kc resident
        __syncthreads();                // all warps past chunk kc-1's buffer
        if (kc + 3 < NC) do_copy(kc + 3, (kc + 3) & (NSTG - 1));
        cp_commit();

        const unsigned stA = sbase + s * ST_BYTES;
        const unsigned stB = stA + A_ST_BYTES;
        #pragma unroll
        for (int ks = 0; ks < 2; ks++) {
            unsigned a[4][4];
            #pragma unroll
            for (int mi = 0; mi < 4; mi++) {
                int row = wm * 64 + mi * 16 + (lane & 15);
                int kb  = ks * 16 + (lane >> 4) * 8;
                ldmx4(a[mi][0], a[mi][1], a[mi][2], a[mi][3],
                      stA + (row * PADK + kb) * 2);
            }
            unsigned b[8][2];
            #pragma unroll
            for (int ng = 0; ng < 4; ng++) {
                int row = wn * 64 + ng * 16 + ((lane >> 4) << 3) + (lane & 7);
                int kb  = ks * 16 + ((lane >> 3) & 1) * 8;
                unsigned r0, r1, r2, r3;
                ldmx4(r0, r1, r2, r3, stB + (row * PADK + kb) * 2);
                b[ng * 2][0] = r0;      b[ng * 2][1] = r1;
                b[ng * 2 + 1][0] = r2;  b[ng * 2 + 1][1] = r3;
            }
            #pragma unroll
            for (int mi = 0; mi < 4; mi++)
                #pragma unroll
                for (int ni = 0; ni < 8; ni++)
                    mma16816(acc[mi][ni], a[mi], b[ni][0], b[ni][1]);
        }
    }

    // epilogue: bias + relu
    #pragma unroll
    for (int mi = 0; mi < 4; mi++) {
        int r0 = tileM + wm * 64 + mi * 16 + (lane >> 2);
        #pragma unroll
        for (int ni = 0; ni < 8; ni++) {
            int c = tileN + wn * 64 + ni * 8 + 2 * (lane & 3);
            float b0 = bias[c], b1 = bias[c + 1];
            float2 v0, v1;
            v0.x = fmaxf(acc[mi][ni][0] + b0, 0.f);
            v0.y = fmaxf(acc[mi][ni][1] + b1, 0.f);
            v1.x = fmaxf(acc[mi][ni][2] + b0, 0.f);
            v1.y = fmaxf(acc[mi][ni][3] + b1, 0.f);
            *reinterpret_cast<float2*>(C + (size_t)r0 * cstride + c) = v0;
            *reinterpret_cast<float2*>(C + (size_t)(r0 + 8) * cstride + c) = v1;
        }
    }
}

// ---------------------------------------------------------------------------
// Prep kernels
// ---------------------------------------------------------------------------
// src fp32 [32768,1024] -> hi/lo bf16 written into [32768,2048] at col base.
__global__ void __launch_bounds__(256) prep_half(
    const float* __restrict__ src,
    __nv_bfloat16* __restrict__ Ahi, __nv_bfloat16* __restrict__ Alo,
    int colbase)
{
    size_t idx = (size_t)blockIdx.x * 256 + threadIdx.x;   // one float4
    size_t row = idx >> 8;
    int    c4  = (int)(idx & 255) * 4;
    const float4 v = *reinterpret_cast<const float4*>(src + row * 1024 + c4);
    const float xs[4] = {v.x, v.y, v.z, v.w};
    ushort4 hv, lv;
    unsigned short* hp = &hv.x;
    unsigned short* lp = &lv.x;
    #pragma unroll
    for (int i = 0; i < 4; i++) {
        __nv_bfloat16 h = __float2bfloat16_rn(xs[i]);
        __nv_bfloat16 l = __float2bfloat16_rn(xs[i] - __bfloat162float(h));
        hp[i] = __bfloat16_as_ushort(h);
        lp[i] = __bfloat16_as_ushort(l);
    }
    size_t o = row * 2048 + colbase + c4;
    *reinterpret_cast<ushort4*>(Ahi + o) = hv;
    *reinterpret_cast<ushort4*>(Alo + o) = lv;
}

__global__ void __launch_bounds__(256) prep_ao(
    const float* __restrict__ AO,
    __nv_bfloat16* __restrict__ Hi, __nv_bfloat16* __restrict__ Lo)
{
    size_t idx = (size_t)blockIdx.x * 256 + threadIdx.x;   // one float4
    const float4 v = *reinterpret_cast<const float4*>(AO + idx * 4);
    const float xs[4] = {v.x, v.y, v.z, v.w};
    ushort4 hv, lv;
    unsigned short* hp = &hv.x;
    unsigned short* lp = &lv.x;
    #pragma unroll
    for (int i = 0; i < 4; i++) {
        __nv_bfloat16 h = __float2bfloat16_rn(xs[i]);
        __nv_bfloat16 l = __float2bfloat16_rn(xs[i] - __bfloat162float(h));
        hp[i] = __bfloat16_as_ushort(h);
        lp[i] = __bfloat16_as_ushort(l);
    }
    *reinterpret_cast<ushort4*>(Hi + idx * 4) = hv;
    *reinterpret_cast<ushort4*>(Lo + idx * 4) = lv;
}

// W [K,1024] fp32 -> WT hi/lo bf16 [1024, K]; blockIdx.z selects (Wq,Wk,Wv).
__global__ void __launch_bounds__(256) prep_wt_qkv(
    const float* __restrict__ W0, const float* __restrict__ W1,
    const float* __restrict__ W2,
    __nv_bfloat16* __restrict__ Thi, __nv_bfloat16* __restrict__ Tlo)
{
    __shared__ float t[32][33];
    const float* W = (blockIdx.z == 0) ? W0 : (blockIdx.z == 1) ? W1 : W2;
    __nv_bfloat16* Hi = Thi + (size_t)blockIdx.z * 1024 * K2;
    __nv_bfloat16* Lo = Tlo + (size_t)blockIdx.z * 1024 * K2;
    const int kb = blockIdx.x * 32, nb = blockIdx.y * 32;
    const int x = threadIdx.x, y = threadIdx.y;
    #pragma unroll
    for (int i = 0; i < 32; i += 8)
        t[y + i][x] = W[(size_t)(kb + y + i) * 1024 + nb + x];
    __syncthreads();
    #pragma unroll
    for (int i = 0; i < 32; i += 8) {
        float v = t[x][y + i];
        __nv_bfloat16 h = __float2bfloat16_rn(v);
        __nv_bfloat16 l = __float2bfloat16_rn(v - __bfloat162float(h));
        size_t o = (size_t)(nb + y + i) * K2 + kb + x;
        Hi[o] = h;
        Lo[o] = l;
    }
}

__global__ void __launch_bounds__(256) prep_wt_o(
    const float* __restrict__ W,
    __nv_bfloat16* __restrict__ Thi, __nv_bfloat16* __restrict__ Tlo)
{
    __shared__ float t[32][33];
    const int kb = blockIdx.x * 32, nb = blockIdx.y * 32;
    const int x = threadIdx.x, y = threadIdx.y;
    #pragma unroll
    for (int i = 0; i < 32; i += 8)
        t[y + i][x] = W[(size_t)(kb + y + i) * 1024 + nb + x];
    __syncthreads();
    #pragma unroll
    for (int i = 0; i < 32; i += 8) {
        float v = t[x][y + i];
        __nv_bfloat16 h = __float2bfloat16_rn(v);
        __nv_bfloat16 l = __float2bfloat16_rn(v - __bfloat162float(h));
        size_t o = (size_t)(nb + y + i) * D_DIM + kb + x;
        Thi[o] = h;
        Tlo[o] = l;
    }
}

__global__ void __launch_bounds__(256) fuse_bias(
    const float* __restrict__ bq, const float* __restrict__ bk,
    const float* __restrict__ bv, float* __restrict__ out)
{
    int i = blockIdx.x * 256 + threadIdx.x;
    if (i < 3072)
        out[i] = (i < 1024) ? bq[i] : (i < 2048) ? bk[i - 1024] : bv[i - 2048];
}

// ---------------------------------------------------------------------------
// Causal attention per (b, n, head); qkv fused [32768, 3072] fp32.
// ---------------------------------------------------------------------------
__global__ void __launch_bounds__(128) attn_kernel(
    const float* __restrict__ QKV, float* __restrict__ O)
{
    __shared__ float qs[64][33];
    __shared__ float ks[64][33];
    __shared__ float vs[64][33];
    __shared__ float ps[64][65];

    const int bid = blockIdx.x;
    const int h = bid & 31;
    const int n = (bid >> 5) & 127;
    const int b = bid >> 12;
    const int tid = threadIdx.x;
    const int lane = tid & 31;
    const int warp = tid >> 5;

    const int hc = h * 32 + lane;

    #pragma unroll
    for (int i = 0; i < 16; i++) {
        int t = warp * 16 + i;
        size_t row = ((size_t)b * 64 + t) * 128 + n;
        const float* r = QKV + row * 3072;
        qs[t][lane] = r[hc];
        ks[t][lane] = r[1024 + hc];
        vs[t][lane] = r[2048 + hc];
    }
    __syncthreads();

    const float scale = 0.17677669529663687f;  // 1/sqrt(32)
    #pragma unroll 1
    for (int i = 0; i < 32; i++) {
        int idx = i * 128 + tid;
        int t = idx >> 6;
        int s = idx & 63;
        if (s <= t) {
            float acc = 0.f;
            #pragma unroll
            for (int kk = 0; kk < 32; kk++)
                acc = fmaf(qs[t][kk], ks[s][kk], acc);
            ps[t][s] = acc * scale;
        }
    }
    __syncthreads();

    #pragma unroll 1
    for (int i = 0; i < 16; i++) {
        int t = warp * 16 + i;
        float x0 = (lane <= t) ? ps[t][lane] : -1e30f;
        float x1 = (lane + 32 <= t) ? ps[t][lane + 32] : -1e30f;
        float m = fmaxf(x0, x1);
        #pragma unroll
        for (int o = 16; o; o >>= 1) m = fmaxf(m, __shfl_xor_sync(0xffffffffu, m, o));
        float e0 = (lane <= t) ? expf(x0 - m) : 0.f;
        float e1 = (lane + 32 <= t) ? expf(x1 - m) : 0.f;
        float sum = e0 + e1;
        #pragma unroll
        for (int o = 16; o; o >>= 1) sum += __shfl_xor_sync(0xffffffffu, sum, o);
        float inv = 1.f / sum;
        ps[t][lane] = e0 * inv;
        ps[t][lane + 32] = e1 * inv;
    }
    __syncthreads();

    #pragma unroll 1
    for (int i = 0; i < 16; i++) {
        int t = warp + 4 * i;
        float acc = 0.f;
        for (int s = 0; s <= t; s++)
            acc = fmaf(ps[t][s], vs[s][lane], acc);
        size_t row = ((size_t)b * 64 + t) * 128 + n;
        O[row * 1024 + hc] = acc;
    }
}

// ---------------------------------------------------------------------------
extern "C" void kernel_launch(void* const* d_in, const int* in_sizes, int n_in,
                              void* d_out, int out_size)
{
    const float* X   = (const float*)d_in[0];
    const float* STE = (const float*)d_in[1];
    const float* Wq  = (const float*)d_in[2];
    const float* bq  = (const float*)d_in[3];
    const float* Wk  = (const float*)d_in[4];
    const float* bk  = (const float*)d_in[5];
    const float* Wv  = (const float*)d_in[6];
    const float* bv  = (const float*)d_in[7];
    const float* Wo  = (const float*)d_in[8];
    const float* bo  = (const float*)d_in[9];
    float* out = (float*)d_out;

    unsigned char* sc = nullptr;
    cudaGetSymbolAddress((void**)&sc, g_scratch);
    float*         qkv   = (float*)(sc + OFF_QKV);
    float*         ao    = (float*)(sc + OFF_AO);
    __nv_bfloat16* Ahi   = (__nv_bfloat16*)(sc + OFF_AHI);
    __nv_bfloat16* Alo   = (__nv_bfloat16*)(sc + OFF_ALO);
    __nv_bfloat16* AOhi  = (__nv_bfloat16*)(sc + OFF_AOHI);
    __nv_bfloat16* AOlo  = (__nv_bfloat16*)(sc + OFF_AOLO);
    __nv_bfloat16* WThi  = (__nv_bfloat16*)(sc + OFF_WTHI);
    __nv_bfloat16* WTlo  = (__nv_bfloat16*)(sc + OFF_WTLO);
    __nv_bfloat16* WOThi = (__nv_bfloat16*)(sc + OFF_WOTHI);
    __nv_bfloat16* WOTlo = (__nv_bfloat16*)(sc + OFF_WOTLO);
    float*         biasF = (float*)(sc + OFF_BIAS);

    cudaFuncSetAttribute(mma_gemm,
                         cudaFuncAttributeMaxDynamicSharedMemorySize,
                         GEMM_SMEM);

    // --- prep (5 launches so the QKV GEMM lands at ncu launch index 5) ---
    prep_half<<<32768, 256>>>(X,   Ahi, Alo, 0);      // launch 0
    prep_half<<<32768, 256>>>(STE, Ahi, Alo, 1024);   // launch 1
    dim3 tb(32, 8);
    prep_wt_qkv<<<dim3(64, 32, 3), tb>>>(Wq, Wk, Wv, WThi, WTlo);  // launch 2
    prep_wt_o<<<dim3(32, 32), tb>>>(Wo, WOThi, WOTlo);             // launch 3
    fuse_bias<<<12, 256>>>(bq, bk, bv, biasF);                     // launch 4

    // --- fused QKV projection (launch 5 -> profiled) ---
    mma_gemm<<<dim3(NEFF / 256, M_TOTAL / 128), 256, GEMM_SMEM>>>(
        Ahi, Alo, WThi, WTlo, biasF, qkv, K2, NEFF);

    // --- causal temporal attention ---
    attn_kernel<<<B_SZ * N_SZ * HEADS, 128>>>(qkv, ao);

    // --- output projection ---
    prep_ao<<<32768, 256>>>(ao, AOhi, AOlo);
    mma_gemm<<<dim3(D_DIM / 256, M_TOTAL / 128), 256, GEMM_SMEM>>>(
        AOhi, AOlo, WOThi, WOTlo, bo, out, D_DIM, D_DIM);
}

// round 8
// speedup vs baseline: 1.4737x; 1.4737x over previous
#include <cuda_runtime.h>
#include <cuda_bf16.h>
#include <math.h>
#include <stdint.h>

// ---------------------------------------------------------------------------
// Problem constants
// ---------------------------------------------------------------------------
#define B_SZ 4
#define T_SZ 64
#define N_SZ 128
#define D_DIM 1024
#define K2 2048
#define M_TOTAL 32768              // B*T*N
#define NEFF 3072                  // fused QKV output cols

// ---------------------------------------------------------------------------
// Scratch carve-out (single __device__ blob; allocation-free rule)
// All fp32 now (tf32-rounded values stored as fp32).
// ---------------------------------------------------------------------------
#define OFF_QKV  ((size_t)0)                        // fp32 [32768,3072]
#define OFF_AO   (OFF_QKV + (size_t)402653184)      // fp32 [32768,1024]
#define OFF_A    (OFF_AO  + (size_t)134217728)      // fp32 [32768,2048] tf32
#define OFF_AOR  (OFF_A   + (size_t)268435456)      // fp32 [32768,1024] tf32
#define OFF_WT   (OFF_AOR + (size_t)134217728)      // fp32 [3072,2048]  tf32
#define OFF_WOT  (OFF_WT  + (size_t)25165824)       // fp32 [1024,1024]  tf32
#define SCRATCH_BYTES (OFF_WOT + (size_t)4194304)

__device__ __align__(1024) unsigned char g_scratch[SCRATCH_BYTES];

// ---------------------------------------------------------------------------
// PTX helpers (base sm_100 features only)
// ---------------------------------------------------------------------------
static __device__ __forceinline__ unsigned smem_u32(const void* p) {
    unsigned r;
    asm("{ .reg .u64 t; cvta.to.shared.u64 t, %1; cvt.u32.u64 %0, t; }"
        : "=r"(r) : "l"(p));
    return r;
}
static __device__ __forceinline__ void cp16(unsigned dst, const void* src) {
    asm volatile("cp.async.cg.shared.global [%0], [%1], 16;"
                 :: "r"(dst), "l"(src) : "memory");
}
static __device__ __forceinline__ void cp_commit() {
    asm volatile("cp.async.commit_group;" ::: "memory");
}
static __device__ __forceinline__ void cp_wait2() {
    asm volatile("cp.async.wait_group 2;" ::: "memory");
}
static __device__ __forceinline__ void ldmx4(
    unsigned& r0, unsigned& r1, unsigned& r2, unsigned& r3, unsigned addr) {
    asm volatile("ldmatrix.sync.aligned.m8n8.x4.shared.b16 {%0,%1,%2,%3}, [%4];"
                 : "=r"(r0), "=r"(r1), "=r"(r2), "=r"(r3) : "r"(addr));
}
static __device__ __forceinline__ void mma_tf32(
    float* c, const unsigned* a, unsigned b0, unsigned b1) {
    asm volatile(
        "mma.sync.aligned.m16n8k8.row.col.f32.tf32.tf32.f32 "
        "{%0,%1,%2,%3}, {%4,%5,%6,%7}, {%8,%9}, {%0,%1,%2,%3};"
        : "+f"(c[0]), "+f"(c[1]), "+f"(c[2]), "+f"(c[3])
        : "r"(a[0]), "r"(a[1]), "r"(a[2]), "r"(a[3]), "r"(b0), "r"(b1));
}
static __device__ __forceinline__ float tf32r(float x) {
    unsigned u;
    asm("cvt.rna.tf32.f32 %0, %1;" : "=r"(u) : "f"(x));
    return __uint_as_float(u);
}

// ---------------------------------------------------------------------------
// tf32 single-pass GEMM via mma.sync.m16n8k8.
// C[M, cstride-window] = relu( A @ WT^T + bias );
// A [M,K] tf32-rounded fp32, WT [N,K] tf32-rounded fp32.
// CTA tile 128x256, BK=16, 8 warps (warptile 64x64), 4-stage cp.async.
// ---------------------------------------------------------------------------
#define PK 20                          // floats per padded smem row (80B)
#define A_ST (128 * PK * 4)            // 10240 B
#define B_ST (256 * PK * 4)            // 20480 B
#define ST_BYTES (A_ST + B_ST)         // 30720 B
#define NSTG 4
#define GEMM_SMEM (NSTG * ST_BYTES)    // 122880 B

__global__ void __launch_bounds__(256, 1) mma_gemm(
    const float* __restrict__ A,
    const float* __restrict__ WT,
    const float* __restrict__ bias0,   // cols [0,1024)
    const float* __restrict__ bias1,   // cols [1024,2048)
    const float* __restrict__ bias2,   // cols [2048,3072)
    float* __restrict__ C,
    int K, int cstride)
{
    extern __shared__ __align__(16) unsigned char smem[];
    const unsigned sbase = smem_u32(smem);

    const int tid  = threadIdx.x;
    const int lane = tid & 31;
    const int warp = tid >> 5;
    const int wm   = warp >> 2;          // 0..1 (64-row slab)
    const int wn   = warp & 3;           // 0..3 (64-col slab)
    const int tileM = blockIdx.y * 128;
    const int tileN = blockIdx.x * 256;

    const int NC = K >> 4;               // 16-wide K chunks

    float acc[4][8][4];
    #pragma unroll
    for (int mi = 0; mi < 4; mi++)
        #pragma unroll
        for (int ni = 0; ni < 8; ni++)
            #pragma unroll
            for (int e = 0; e < 4; e++) acc[mi][ni][e] = 0.f;

    // copy chunk kc into stage s. A: 128x16 f32 (2 cp/thread); B: 256x16 (4)
    auto do_copy = [&](int kc, int s) {
        const int klocal = kc << 4;
        const unsigned stA = sbase + s * ST_BYTES;
        const unsigned stB = stA + A_ST;
        #pragma unroll
        for (int i = 0; i < 2; i++) {
            int idx = tid + i * 256;          // 0..511
            int r = idx >> 2, seg = idx & 3;  // seg: 4-float (16B) segment
            cp16(stA + (r * PK + seg * 4) * 4,
                 A + (size_t)(tileM + r) * K + klocal + seg * 4);
        }
        #pragma unroll
        for (int i = 0; i < 4; i++) {
            int idx = tid + i * 256;          // 0..1023
            int r = idx >> 2, seg = idx & 3;
            cp16(stB + (r * PK + seg * 4) * 4,
                 WT + (size_t)(tileN + r) * K + klocal + seg * 4);
        }
    };

    #pragma unroll
    for (int p = 0; p < 3; p++) { do_copy(p, p); cp_commit(); }

    // per-lane ldmatrix row offsets (b16-tile trick: 8x8 b16 == 8x4 tf32)
    const int aRow = (lane & 7) + (lane & 8);          // m within 16
    const int aKof = (lane & 16) ? 4 : 0;              // k within 8
    const int bRow = (lane & 7) + ((lane & 16) ? 8 : 0);
    const int bKof = (lane & 8) ? 4 : 0;

    for (int kc = 0; kc < NC; kc++) {
        const int s = kc & (NSTG - 1);
        cp_wait2();                     // chunk kc resident
        __syncthreads();                // all warps done with stage being reused
        if (kc + 3 < NC) do_copy(kc + 3, (kc + 3) & (NSTG - 1));
        cp_commit();

        const unsigned stA = sbase + s * ST_BYTES;
        const unsigned stB = stA + A_ST;
        #pragma unroll
        for (int ks = 0; ks < 2; ks++) {     // two k8 steps per 16-chunk
            const int kb = ks * 8;
            unsigned a[4][4];
            #pragma unroll
            for (int mi = 0; mi < 4; mi++) {
                int row = wm * 64 + mi * 16 + aRow;
                ldmx4(a[mi][0], a[mi][1], a[mi][2], a[mi][3],
                      stA + (row * PK + kb + aKof) * 4);
            }
            unsigned b[8][2];
            #pragma unroll
            for (int ng = 0; ng < 4; ng++) {
                int row = wn * 64 + ng * 16 + bRow;
                unsigned r0, r1, r2, r3;
                ldmx4(r0, r1, r2, r3, stB + (row * PK + kb + bKof) * 4);
                b[ng * 2][0] = r0;      b[ng * 2][1] = r1;
                b[ng * 2 + 1][0] = r2;  b[ng * 2 + 1][1] = r3;
            }
            #pragma unroll
            for (int mi = 0; mi < 4; mi++)
                #pragma unroll
                for (int ni = 0; ni < 8; ni++)
                    mma_tf32(acc[mi][ni], a[mi], b[ni][0], b[ni][1]);
        }
    }

    // epilogue: bias + relu
    #pragma unroll
    for (int mi = 0; mi < 4; mi++) {
        int r0 = tileM + wm * 64 + mi * 16 + (lane >> 2);
        #pragma unroll
        for (int ni = 0; ni < 8; ni++) {
            int c = tileN + wn * 64 + ni * 8 + 2 * (lane & 3);
            const float* bp = (c < 1024) ? bias0 : (c < 2048) ? bias1 : bias2;
            float b0 = bp[c & 1023], b1 = bp[(c + 1) & 1023];
            float2 v0, v1;
            v0.x = fmaxf(acc[mi][ni][0] + b0, 0.f);
            v0.y = fmaxf(acc[mi][ni][1] + b1, 0.f);
            v1.x = fmaxf(acc[mi][ni][2] + b0, 0.f);
            v1.y = fmaxf(acc[mi][ni][3] + b1, 0.f);
            *reinterpret_cast<float2*>(C + (size_t)r0 * cstride + c) = v0;
            *reinterpret_cast<float2*>(C + (size_t)(r0 + 8) * cstride + c) = v1;
        }
    }
}

// ---------------------------------------------------------------------------
// Prep kernels (tf32 rounding)
// ---------------------------------------------------------------------------
// [X|STE] -> A [32768,2048] tf32-rounded fp32
__global__ void __launch_bounds__(256) prep_a(
    const float* __restrict__ X, const float* __restrict__ STE,
    float* __restrict__ A)
{
    size_t idx = (size_t)blockIdx.x * 256 + threadIdx.x;   // one float4
    size_t row = idx >> 9;
    int    c4  = (int)(idx & 511) * 4;
    const float4 v = (c4 < 1024)
        ? *reinterpret_cast<const float4*>(X + row * 1024 + c4)
        : *reinterpret_cast<const float4*>(STE + row * 1024 + (c4 - 1024));
    float4 o;
    o.x = tf32r(v.x); o.y = tf32r(v.y); o.z = tf32r(v.z); o.w = tf32r(v.w);
    *reinterpret_cast<float4*>(A + row * 2048 + c4) = o;
}

// ao fp32 -> tf32-rounded fp32
__global__ void __launch_bounds__(256) prep_ao(
    const float* __restrict__ AO, float* __restrict__ AOR)
{
    size_t idx = (size_t)blockIdx.x * 256 + threadIdx.x;
    const float4 v = *reinterpret_cast<const float4*>(AO + idx * 4);
    float4 o;
    o.x = tf32r(v.x); o.y = tf32r(v.y); o.z = tf32r(v.z); o.w = tf32r(v.w);
    *reinterpret_cast<float4*>(AOR + idx * 4) = o;
}

// W [K,1024] -> WT [1024,K] tf32-rounded; blockIdx.z selects (Wq,Wk,Wv)
__global__ void __launch_bounds__(256) prep_wt_qkv(
    const float* __restrict__ W0, const float* __restrict__ W1,
    const float* __restrict__ W2, float* __restrict__ WT)
{
    __shared__ float t[32][33];
    const float* W = (blockIdx.z == 0) ? W0 : (blockIdx.z == 1) ? W1 : W2;
    float* O = WT + (size_t)blockIdx.z * 1024 * K2;
    const int kb = blockIdx.x * 32, nb = blockIdx.y * 32;
    const int x = threadIdx.x, y = threadIdx.y;
    #pragma unroll
    for (int i = 0; i < 32; i += 8)
        t[y + i][x] = W[(size_t)(kb + y + i) * 1024 + nb + x];
    __syncthreads();
    #pragma unroll
    for (int i = 0; i < 32; i += 8)
        O[(size_t)(nb + y + i) * K2 + kb + x] = tf32r(t[x][y + i]);
}

__global__ void __launch_bounds__(256) prep_wt_o(
    const float* __restrict__ W, float* __restrict__ WT)
{
    __shared__ float t[32][33];
    const int kb = blockIdx.x * 32, nb = blockIdx.y * 32;
    const int x = threadIdx.x, y = threadIdx.y;
    #pragma unroll
    for (int i = 0; i < 32; i += 8)
        t[y + i][x] = W[(size_t)(kb + y + i) * 1024 + nb + x];
    __syncthreads();
    #pragma unroll
    for (int i = 0; i < 32; i += 8)
        WT[(size_t)(nb + y + i) * D_DIM + kb + x] = tf32r(t[x][y + i]);
}

// ---------------------------------------------------------------------------
// Causal attention per (b, n, head); qkv fused [32768, 3072] fp32.
// ---------------------------------------------------------------------------
__global__ void __launch_bounds__(128) attn_kernel(
    const float* __restrict__ QKV, float* __restrict__ O)
{
    __shared__ float qs[64][33];
    __shared__ float ks[64][33];
    __shared__ float vs[64][33];
    __shared__ float ps[64][65];

    const int bid = blockIdx.x;
    const int h = bid & 31;
    const int n = (bid >> 5) & 127;
    const int b = bid >> 12;
    const int tid = threadIdx.x;
    const int lane = tid & 31;
    const int warp = tid >> 5;

    const int hc = h * 32 + lane;

    #pragma unroll
    for (int i = 0; i < 16; i++) {
        int t = warp * 16 + i;
        size_t row = ((size_t)b * 64 + t) * 128 + n;
        const float* r = QKV + row * 3072;
        qs[t][lane] = r[hc];
        ks[t][lane] = r[1024 + hc];
        vs[t][lane] = r[2048 + hc];
    }
    __syncthreads();

    const float scale = 0.17677669529663687f;  // 1/sqrt(32)
    #pragma unroll 1
    for (int i = 0; i < 32; i++) {
        int idx = i * 128 + tid;
        int t = idx >> 6;
        int s = idx & 63;
        if (s <= t) {
            float acc = 0.f;
            #pragma unroll
            for (int kk = 0; kk < 32; kk++)
                acc = fmaf(qs[t][kk], ks[s][kk], acc);
            ps[t][s] = acc * scale;
        }
    }
    __syncthreads();

    #pragma unroll 1
    for (int i = 0; i < 16; i++) {
        int t = warp * 16 + i;
        float x0 = (lane <= t) ? ps[t][lane] : -1e30f;
        float x1 = (lane + 32 <= t) ? ps[t][lane + 32] : -1e30f;
        float m = fmaxf(x0, x1);
        #pragma unroll
        for (int o = 16; o; o >>= 1) m = fmaxf(m, __shfl_xor_sync(0xffffffffu, m, o));
        float e0 = (lane <= t) ? expf(x0 - m) : 0.f;
        float e1 = (lane + 32 <= t) ? expf(x1 - m) : 0.f;
        float sum = e0 + e1;
        #pragma unroll
        for (int o = 16; o; o >>= 1) sum += __shfl_xor_sync(0xffffffffu, sum, o);
        float inv = 1.f / sum;
        ps[t][lane] = e0 * inv;
        ps[t][lane + 32] = e1 * inv;
    }
    __syncthreads();

    #pragma unroll 1
    for (int i = 0; i < 16; i++) {
        int t = warp + 4 * i;
        float acc = 0.f;
        for (int s = 0; s <= t; s++)
            acc = fmaf(ps[t][s], vs[s][lane], acc);
        size_t row = ((size_t)b * 64 + t) * 128 + n;
        O[row * 1024 + hc] = acc;
    }
}

// ---------------------------------------------------------------------------
extern "C" void kernel_launch(void* const* d_in, const int* in_sizes, int n_in,
                              void* d_out, int out_size)
{
    const float* X   = (const float*)d_in[0];
    const float* STE = (const float*)d_in[1];
    const float* Wq  = (const float*)d_in[2];
    const float* bq  = (const float*)d_in[3];
    const float* Wk  = (const float*)d_in[4];
    const float* bk  = (const float*)d_in[5];
    const float* Wv  = (const float*)d_in[6];
    const float* bv  = (const float*)d_in[7];
    const float* Wo  = (const float*)d_in[8];
    const float* bo  = (const float*)d_in[9];
    float* out = (float*)d_out;

    unsigned char* sc = nullptr;
    cudaGetSymbolAddress((void**)&sc, g_scratch);
    float* qkv = (float*)(sc + OFF_QKV);
    float* ao  = (float*)(sc + OFF_AO);
    float* A   = (float*)(sc + OFF_A);
    float* AOR = (float*)(sc + OFF_AOR);
    float* WT  = (float*)(sc + OFF_WT);
    float* WOT = (float*)(sc + OFF_WOT);

    cudaFuncSetAttribute(mma_gemm,
                         cudaFuncAttributeMaxDynamicSharedMemorySize,
                         GEMM_SMEM);

    dim3 tb(32, 8);
    prep_a<<<65536, 256>>>(X, STE, A);                        // launch 0
    prep_wt_qkv<<<dim3(64, 32, 3), tb>>>(Wq, Wk, Wv, WT);     // launch 1
    prep_wt_o<<<dim3(32, 32), tb>>>(Wo, WOT);                 // launch 2

    // launch 3 (profiled): fused QKV projection
    mma_gemm<<<dim3(NEFF / 256, M_TOTAL / 128), 256, GEMM_SMEM>>>(
        A, WT, bq, bk, bv, qkv, K2, NEFF);

    // causal temporal attention
    attn_kernel<<<B_SZ * N_SZ * 32, 128>>>(qkv, ao);

    // output projection
    prep_ao<<<32768, 256>>>(ao, AOR);
    mma_gemm<<<dim3(D_DIM / 256, M_TOTAL / 128), 256, GEMM_SMEM>>>(
        AOR, WOT, bo, bo, bo, out, D_DIM, D_DIM);
}

// round 9
// speedup vs baseline: 1.7104x; 1.1606x over previous
#include <cuda_runtime.h>
#include <cuda_bf16.h>
#include <math.h>
#include <stdint.h>

// ---------------------------------------------------------------------------
// Problem constants
// ---------------------------------------------------------------------------
#define B_SZ 4
#define T_SZ 64
#define N_SZ 128
#define D_DIM 1024
#define K2 2048
#define M_TOTAL 32768              // B*T*N
#define NEFF 3072                  // fused QKV output cols

// ---------------------------------------------------------------------------
// Scratch carve-out (single __device__ blob; allocation-free rule)
// ---------------------------------------------------------------------------
#define OFF_QKV  ((size_t)0)                        // fp32 [32768,3072]
#define OFF_A    (OFF_QKV + (size_t)402653184)      // fp32 [32768,2048] tf32
#define OFF_AOR  (OFF_A   + (size_t)268435456)      // fp32 [32768,1024] tf32
#define OFF_WT   (OFF_AOR + (size_t)134217728)      // fp32 [3072,2048]  tf32
#define OFF_WOT  (OFF_WT  + (size_t)25165824)       // fp32 [1024,1024]  tf32
#define SCRATCH_BYTES (OFF_WOT + (size_t)4194304)

__device__ __align__(1024) unsigned char g_scratch[SCRATCH_BYTES];

// ---------------------------------------------------------------------------
// PTX helpers (base sm_100 features only)
// ---------------------------------------------------------------------------
static __device__ __forceinline__ unsigned smem_u32(const void* p) {
    unsigned r;
    asm("{ .reg .u64 t; cvta.to.shared.u64 t, %1; cvt.u32.u64 %0, t; }"
        : "=r"(r) : "l"(p));
    return r;
}
static __device__ __forceinline__ void cp16(unsigned dst, const void* src) {
    asm volatile("cp.async.cg.shared.global [%0], [%1], 16;"
                 :: "r"(dst), "l"(src) : "memory");
}
static __device__ __forceinline__ void cp_commit() {
    asm volatile("cp.async.commit_group;" ::: "memory");
}
static __device__ __forceinline__ void cp_wait2() {
    asm volatile("cp.async.wait_group 2;" ::: "memory");
}
static __device__ __forceinline__ void ldmx4(
    unsigned& r0, unsigned& r1, unsigned& r2, unsigned& r3, unsigned addr) {
    asm volatile("ldmatrix.sync.aligned.m8n8.x4.shared.b16 {%0,%1,%2,%3}, [%4];"
                 : "=r"(r0), "=r"(r1), "=r"(r2), "=r"(r3) : "r"(addr));
}
static __device__ __forceinline__ void mma_tf32(
    float* c, const unsigned* a, unsigned b0, unsigned b1) {
    asm volatile(
        "mma.sync.aligned.m16n8k8.row.col.f32.tf32.tf32.f32 "
        "{%0,%1,%2,%3}, {%4,%5,%6,%7}, {%8,%9}, {%0,%1,%2,%3};"
        : "+f"(c[0]), "+f"(c[1]), "+f"(c[2]), "+f"(c[3])
        : "r"(a[0]), "r"(a[1]), "r"(a[2]), "r"(a[3]), "r"(b0), "r"(b1));
}
static __device__ __forceinline__ float tf32r(float x) {
    unsigned u;
    asm("cvt.rna.tf32.f32 %0, %1;" : "=r"(u) : "f"(x));
    return __uint_as_float(u);
}

// ---------------------------------------------------------------------------
// tf32 single-pass GEMM via mma.sync.m16n8k8.
// C[M, cstride-window] = relu( A @ WT^T + bias );
// CTA tile 128x128, BK=16, 8 warps (warptile 64x32), 4-stage cp.async,
// 2 CTAs/SM for tensor-pipe latency hiding.
// ---------------------------------------------------------------------------
#define PK 20                          // floats per padded smem row (80B)
#define A_ST (128 * PK * 4)            // 10240 B
#define B_ST (128 * PK * 4)            // 10240 B
#define ST_BYTES (A_ST + B_ST)         // 20480 B
#define NSTG 4
#define GEMM_SMEM (NSTG * ST_BYTES)    // 81920 B per CTA

__global__ void __launch_bounds__(256, 2) mma_gemm(
    const float* __restrict__ A,
    const float* __restrict__ WT,
    const float* __restrict__ bias0,   // cols [0,1024)
    const float* __restrict__ bias1,   // cols [1024,2048)
    const float* __restrict__ bias2,   // cols [2048,3072)
    float* __restrict__ C,
    int K, int cstride)
{
    extern __shared__ __align__(16) unsigned char smem[];
    const unsigned sbase = smem_u32(smem);

    const int tid  = threadIdx.x;
    const int lane = tid & 31;
    const int warp = tid >> 5;
    const int wm   = warp >> 2;          // 0..1 (64-row slab)
    const int wn   = warp & 3;           // 0..3 (32-col slab)
    const int tileM = blockIdx.y * 128;
    const int tileN = blockIdx.x * 128;

    const int NC = K >> 4;               // 16-wide K chunks

    float acc[4][4][4];
    #pragma unroll
    for (int mi = 0; mi < 4; mi++)
        #pragma unroll
        for (int ni = 0; ni < 4; ni++)
            #pragma unroll
            for (int e = 0; e < 4; e++) acc[mi][ni][e] = 0.f;

    // copy chunk kc into stage s. A,B each 128x16 f32: 2 cp16/thread
    auto do_copy = [&](int kc, int s) {
        const int klocal = kc << 4;
        const unsigned stA = sbase + s * ST_BYTES;
        const unsigned stB = stA + A_ST;
        #pragma unroll
        for (int i = 0; i < 2; i++) {
            int idx = tid + i * 256;          // 0..511
            int r = idx >> 2, seg = idx & 3;  // 16B segment
            cp16(stA + (r * PK + seg * 4) * 4,
                 A + (size_t)(tileM + r) * K + klocal + seg * 4);
        }
        #pragma unroll
        for (int i = 0; i < 2; i++) {
            int idx = tid + i * 256;
            int r = idx >> 2, seg = idx & 3;
            cp16(stB + (r * PK + seg * 4) * 4,
                 WT + (size_t)(tileN + r) * K + klocal + seg * 4);
        }
    };

    #pragma unroll
    for (int p = 0; p < 3; p++) { do_copy(p, p); cp_commit(); }

    // per-lane ldmatrix row offsets (b16-tile trick: 8x8 b16 == 8x4 tf32)
    const int aRow = (lane & 7) + (lane & 8);          // m within 16
    const int aKof = (lane & 16) ? 4 : 0;              // k within 8
    const int bRow = (lane & 7) + ((lane & 16) ? 8 : 0);
    const int bKof = (lane & 8) ? 4 : 0;

    for (int kc = 0; kc < NC; kc++) {
        const int s = kc & (NSTG - 1);
        cp_wait2();                     // chunk kc resident
        __syncthreads();                // all warps done with stage being reused
        if (kc + 3 < NC) do_copy(kc + 3, (kc + 3) & (NSTG - 1));
        cp_commit();

        const unsigned stA = sbase + s * ST_BYTES;
        const unsigned stB = stA + A_ST;
        #pragma unroll
        for (int ks = 0; ks < 2; ks++) {     // two k8 steps per 16-chunk
            const int kb = ks * 8;
            unsigned a[4][4];
            #pragma unroll
            for (int mi = 0; mi < 4; mi++) {
                int row = wm * 64 + mi * 16 + aRow;
                ldmx4(a[mi][0], a[mi][1], a[mi][2], a[mi][3],
                      stA + (row * PK + kb + aKof) * 4);
            }
            unsigned b[4][2];
            #pragma unroll
            for (int ng = 0; ng < 2; ng++) {
                int row = wn * 32 + ng * 16 + bRow;
                unsigned r0, r1, r2, r3;
                ldmx4(r0, r1, r2, r3, stB + (row * PK + kb + bKof) * 4);
                b[ng * 2][0] = r0;      b[ng * 2][1] = r1;
                b[ng * 2 + 1][0] = r2;  b[ng * 2 + 1][1] = r3;
            }
            #pragma unroll
            for (int mi = 0; mi < 4; mi++)
                #pragma unroll
                for (int ni = 0; ni < 4; ni++)
                    mma_tf32(acc[mi][ni], a[mi], b[ni][0], b[ni][1]);
        }
    }

    // epilogue: bias + relu
    #pragma unroll
    for (int mi = 0; mi < 4; mi++) {
        int r0 = tileM + wm * 64 + mi * 16 + (lane >> 2);
        #pragma unroll
        for (int ni = 0; ni < 4; ni++) {
            int c = tileN + wn * 32 + ni * 8 + 2 * (lane & 3);
            const float* bp = (c < 1024) ? bias0 : (c < 2048) ? bias1 : bias2;
            float b0 = bp[c & 1023], b1 = bp[(c + 1) & 1023];
            float2 v0, v1;
            v0.x = fmaxf(acc[mi][ni][0] + b0, 0.f);
            v0.y = fmaxf(acc[mi][ni][1] + b1, 0.f);
            v1.x = fmaxf(acc[mi][ni][2] + b0, 0.f);
            v1.y = fmaxf(acc[mi][ni][3] + b1, 0.f);
            *reinterpret_cast<float2*>(C + (size_t)r0 * cstride + c) = v0;
            *reinterpret_cast<float2*>(C + (size_t)(r0 + 8) * cstride + c) = v1;
        }
    }
}

// ---------------------------------------------------------------------------
// Prep kernels (tf32 rounding)
// ---------------------------------------------------------------------------
__global__ void __launch_bounds__(256) prep_a(
    const float* __restrict__ X, const float* __restrict__ STE,
    float* __restrict__ A)
{
    size_t idx = (size_t)blockIdx.x * 256 + threadIdx.x;   // one float4
    size_t row = idx >> 9;
    int    c4  = (int)(idx & 511) * 4;
    const float4 v = (c4 < 1024)
        ? *reinterpret_cast<const float4*>(X + row * 1024 + c4)
        : *reinterpret_cast<const float4*>(STE + row * 1024 + (c4 - 1024));
    float4 o;
    o.x = tf32r(v.x); o.y = tf32r(v.y); o.z = tf32r(v.z); o.w = tf32r(v.w);
    *reinterpret_cast<float4*>(A + row * 2048 + c4) = o;
}

// W [K,1024] -> WT [1024,K] tf32-rounded; blockIdx.z selects (Wq,Wk,Wv)
__global__ void __launch_bounds__(256) prep_wt_qkv(
    const float* __restrict__ W0, const float* __restrict__ W1,
    const float* __restrict__ W2, float* __restrict__ WT)
{
    __shared__ float t[32][33];
    const float* W = (blockIdx.z == 0) ? W0 : (blockIdx.z == 1) ? W1 : W2;
    float* O = WT + (size_t)blockIdx.z * 1024 * K2;
    const int kb = blockIdx.x * 32, nb = blockIdx.y * 32;
    const int x = threadIdx.x, y = threadIdx.y;
    #pragma unroll
    for (int i = 0; i < 32; i += 8)
        t[y + i][x] = W[(size_t)(kb + y + i) * 1024 + nb + x];
    __syncthreads();
    #pragma unroll
    for (int i = 0; i < 32; i += 8)
        O[(size_t)(nb + y + i) * K2 + kb + x] = tf32r(t[x][y + i]);
}

__global__ void __launch_bounds__(256) prep_wt_o(
    const float* __restrict__ W, float* __restrict__ WT)
{
    __shared__ float t[32][33];
    const int kb = blockIdx.x * 32, nb = blockIdx.y * 32;
    const int x = threadIdx.x, y = threadIdx.y;
    #pragma unroll
    for (int i = 0; i < 32; i += 8)
        t[y + i][x] = W[(size_t)(kb + y + i) * 1024 + nb + x];
    __syncthreads();
    #pragma unroll
    for (int i = 0; i < 32; i += 8)
        WT[(size_t)(nb + y + i) * D_DIM + kb + x] = tf32r(t[x][y + i]);
}

// ---------------------------------------------------------------------------
// Causal attention per (b, n, head); qkv fused [32768, 3072] fp32.
// Output written tf32-rounded (feeds the Wo GEMM directly).
// ---------------------------------------------------------------------------
__global__ void __launch_bounds__(128) attn_kernel(
    const float* __restrict__ QKV, float* __restrict__ O)
{
    __shared__ float qs[64][33];
    __shared__ float ks[64][33];
    __shared__ float vs[64][33];
    __shared__ float ps[64][65];

    const int bid = blockIdx.x;
    const int h = bid & 31;
    const int n = (bid >> 5) & 127;
    const int b = bid >> 12;
    const int tid = threadIdx.x;
    const int lane = tid & 31;
    const int warp = tid >> 5;

    const int hc = h * 32 + lane;

    #pragma unroll
    for (int i = 0; i < 16; i++) {
        int t = warp * 16 + i;
        size_t row = ((size_t)b * 64 + t) * 128 + n;
        const float* r = QKV + row * 3072;
        qs[t][lane] = r[hc];
        ks[t][lane] = r[1024 + hc];
        vs[t][lane] = r[2048 + hc];
    }
    __syncthreads();

    const float scale = 0.17677669529663687f;  // 1/sqrt(32)
    #pragma unroll 1
    for (int i = 0; i < 32; i++) {
        int idx = i * 128 + tid;
        int t = idx >> 6;
        int s = idx & 63;
        if (s <= t) {
            float acc = 0.f;
            #pragma unroll
            for (int kk = 0; kk < 32; kk++)
                acc = fmaf(qs[t][kk], ks[s][kk], acc);
            ps[t][s] = acc * scale;
        }
    }
    __syncthreads();

    #pragma unroll 1
    for (int i = 0; i < 16; i++) {
        int t = warp * 16 + i;
        float x0 = (lane <= t) ? ps[t][lane] : -1e30f;
        float x1 = (lane + 32 <= t) ? ps[t][lane + 32] : -1e30f;
        float m = fmaxf(x0, x1);
        #pragma unroll
        for (int o = 16; o; o >>= 1) m = fmaxf(m, __shfl_xor_sync(0xffffffffu, m, o));
        float e0 = (lane <= t) ? expf(x0 - m) : 0.f;
        float e1 = (lane + 32 <= t) ? expf(x1 - m) : 0.f;
        float sum = e0 + e1;
        #pragma unroll
        for (int o = 16; o; o >>= 1) sum += __shfl_xor_sync(0xffffffffu, sum, o);
        float inv = 1.f / sum;
        ps[t][lane] = e0 * inv;
        ps[t][lane + 32] = e1 * inv;
    }
    __syncthreads();

    #pragma unroll 1
    for (int i = 0; i < 16; i++) {
        int t = warp + 4 * i;
        float acc = 0.f;
        for (int s = 0; s <= t; s++)
            acc = fmaf(ps[t][s], vs[s][lane], acc);
        size_t row = ((size_t)b * 64 + t) * 128 + n;
        O[row * 1024 + hc] = tf32r(acc);
    }
}

// ---------------------------------------------------------------------------
extern "C" void kernel_launch(void* const* d_in, const int* in_sizes, int n_in,
                              void* d_out, int out_size)
{
    const float* X   = (const float*)d_in[0];
    const float* STE = (const float*)d_in[1];
    const float* Wq  = (const float*)d_in[2];
    const float* bq  = (const float*)d_in[3];
    const float* Wk  = (const float*)d_in[4];
    const float* bk  = (const float*)d_in[5];
    const float* Wv  = (const float*)d_in[6];
    const float* bv  = (const float*)d_in[7];
    const float* Wo  = (const float*)d_in[8];
    const float* bo  = (const float*)d_in[9];
    float* out = (float*)d_out;

    unsigned char* sc = nullptr;
    cudaGetSymbolAddress((void**)&sc, g_scratch);
    float* qkv = (float*)(sc + OFF_QKV);
    float* A   = (float*)(sc + OFF_A);
    float* AOR = (float*)(sc + OFF_AOR);
    float* WT  = (float*)(sc + OFF_WT);
    float* WOT = (float*)(sc + OFF_WOT);

    cudaFuncSetAttribute(mma_gemm,
                         cudaFuncAttributeMaxDynamicSharedMemorySize,
                         GEMM_SMEM);

    dim3 tb(32, 8);
    prep_a<<<65536, 256>>>(X, STE, A);                        // launch 0
    prep_wt_qkv<<<dim3(64, 32, 3), tb>>>(Wq, Wk, Wv, WT);     // launch 1
    prep_wt_o<<<dim3(32, 32), tb>>>(Wo, WOT);                 // launch 2

    // launch 3 (profiled): fused QKV projection
    mma_gemm<<<dim3(NEFF / 128, M_TOTAL / 128), 256, GEMM_SMEM>>>(
        A, WT, bq, bk, bv, qkv, K2, NEFF);

    // causal temporal attention (writes tf32-rounded output)
    attn_kernel<<<B_SZ * N_SZ * 32, 128>>>(qkv, AOR);

    // output projection
    mma_gemm<<<dim3(D_DIM / 128, M_TOTAL / 128), 256, GEMM_SMEM>>>(
        AOR, WOT, bo, bo, bo, out, D_DIM, D_DIM);
}